// round 6
// baseline (speedup 1.0000x reference)
#include <cuda_runtime.h>
#include <math.h>

// Problem constants
constexpr int BATCH = 128;
constexpr int SEQT  = 24;
constexpr int EMB   = 512;
constexpr int HID   = 1024;
constexpr int VOC   = 12000;
constexpr int MALL  = SEQT * BATCH;   // 3072 (row m = t*128 + b)
constexpr int G4    = 4 * HID;        // 4096

// Scratch (device globals: allocation is forbidden)
__device__ float g_xall[(size_t)MALL * EMB];   // gathered inputs  [3072, 512]   6.3 MB
__device__ float g_gpre[(size_t)MALL * G4];    // input-proj gates [3072, 4096] 50.3 MB
__device__ float g_allh[(size_t)MALL * HID];   // all hidden states[3072, 1024] 12.6 MB
__device__ float g_cbuf[2 * BATCH * HID];      // double-buffered cell state     1.0 MB

// ---------------------------------------------------------------------------
// Gather: X_all[t*128+b] = (t==0) ? encoder_output[b] : embed_table[captions[b][t-1]]
// ---------------------------------------------------------------------------
__global__ void gather_x_kernel(const float* __restrict__ enc,
                                const int*   __restrict__ caps,
                                const float* __restrict__ emb)
{
    const int m = blockIdx.x;          // 0..3071
    const int t = m >> 7;
    const int b = m & 127;
    const float* src = (t == 0)
        ? (enc + (size_t)b * EMB)
        : (emb + (size_t)caps[b * SEQT + (t - 1)] * EMB);
    float4* dst = reinterpret_cast<float4*>(g_xall + (size_t)m * EMB);
    dst[threadIdx.x] = reinterpret_cast<const float4*>(src)[threadIdx.x];  // 128 thr * 4 = 512
}

// ---------------------------------------------------------------------------
// SGEMM: C[M,N] = A[M,K] @ W[N,K]^T (+ b1 + b2)
//   128x128 tile, BK=8, 256 threads, 8x8 per-thread (split 4+4 for coalescing)
//   mode 0: C row-major [M,N]
//   mode 1: FC epilogue — m = t*128+b, write C[(b*SEQT+t)*N + n]
// ---------------------------------------------------------------------------
__global__ void __launch_bounds__(256)
sgemm_nt_kernel(const float* __restrict__ A, const float* __restrict__ Wt,
                const float* __restrict__ b1, const float* __restrict__ b2,
                float* __restrict__ C, int M, int N, int K, int mode)
{
    __shared__ float As[8][128];
    __shared__ float Ws[8][128];

    const int tid = threadIdx.x;
    const int m0 = blockIdx.y * 128;
    const int n0 = blockIdx.x * 128;
    const int lr = tid >> 1;            // load row in tile 0..127
    const int lc = (tid & 1) * 4;       // load k offset 0/4
    const int tx = tid & 15;            // col thread 0..15
    const int ty = tid >> 4;            // row thread 0..15

    float acc[8][8];
#pragma unroll
    for (int i = 0; i < 8; i++)
#pragma unroll
        for (int j = 0; j < 8; j++) acc[i][j] = 0.f;

    const float* aPtr = A + (size_t)(m0 + lr) * K + lc;       // M always %128==0
    const bool wOk = (n0 + lr) < N;
    const float* wPtr = Wt + (size_t)(wOk ? (n0 + lr) : 0) * K + lc;

    for (int k0 = 0; k0 < K; k0 += 8) {
        const float4 av = *reinterpret_cast<const float4*>(aPtr + k0);
        float4 wv = make_float4(0.f, 0.f, 0.f, 0.f);
        if (wOk) wv = *reinterpret_cast<const float4*>(wPtr + k0);
        As[lc + 0][lr] = av.x; As[lc + 1][lr] = av.y;
        As[lc + 2][lr] = av.z; As[lc + 3][lr] = av.w;
        Ws[lc + 0][lr] = wv.x; Ws[lc + 1][lr] = wv.y;
        Ws[lc + 2][lr] = wv.z; Ws[lc + 3][lr] = wv.w;
        __syncthreads();
#pragma unroll
        for (int kk = 0; kk < 8; kk++) {
            float a[8], w[8];
            *reinterpret_cast<float4*>(&a[0]) = *reinterpret_cast<const float4*>(&As[kk][ty * 4]);
            *reinterpret_cast<float4*>(&a[4]) = *reinterpret_cast<const float4*>(&As[kk][64 + ty * 4]);
            *reinterpret_cast<float4*>(&w[0]) = *reinterpret_cast<const float4*>(&Ws[kk][tx * 4]);
            *reinterpret_cast<float4*>(&w[4]) = *reinterpret_cast<const float4*>(&Ws[kk][64 + tx * 4]);
#pragma unroll
            for (int i = 0; i < 8; i++)
#pragma unroll
                for (int j = 0; j < 8; j++)
                    acc[i][j] = fmaf(a[i], w[j], acc[i][j]);
        }
        __syncthreads();
    }

#pragma unroll
    for (int ih = 0; ih < 2; ih++)
#pragma unroll
        for (int i2 = 0; i2 < 4; i2++) {
            const int i = ih * 4 + i2;
            const int m = m0 + ih * 64 + ty * 4 + i2;
            size_t rowBase;
            if (mode == 0) {
                rowBase = (size_t)m * N;
            } else {
                const int tt = m >> 7, bb = m & 127;
                rowBase = ((size_t)bb * SEQT + tt) * N;
            }
#pragma unroll
            for (int jh = 0; jh < 2; jh++) {
                const int n = n0 + jh * 64 + tx * 4;
                if (n >= N) continue;   // N%4==0, n 4-aligned -> whole float4 valid
                float4 v;
                v.x = acc[i][jh * 4 + 0];
                v.y = acc[i][jh * 4 + 1];
                v.z = acc[i][jh * 4 + 2];
                v.w = acc[i][jh * 4 + 3];
                if (b1) { v.x += b1[n]; v.y += b1[n + 1]; v.z += b1[n + 2]; v.w += b1[n + 3]; }
                if (b2) { v.x += b2[n]; v.y += b2[n + 1]; v.z += b2[n + 2]; v.w += b2[n + 3]; }
                *reinterpret_cast<float4*>(C + rowBase + n) = v;
            }
        }
}

// ---------------------------------------------------------------------------
// Recurrent step t: for n-columns [n0, n0+8) x 4 gates:
//   gates = G_pre[t] + h_{t-1} @ W_hh^T ; then fused LSTM cell update.
//   h_{t-1} read from g_allh[t-1] (zeros at t==0), c double-buffered in g_cbuf.
//   Grid: 128 blocks x 128 threads. Per block: C[128,32] += H[128,1024]@Wsel^T.
// ---------------------------------------------------------------------------
__global__ void __launch_bounds__(128)
lstm_step_kernel(const float* __restrict__ Whh, int t)
{
    __shared__ float Hs[16][128];      // 8 KB
    __shared__ float Ws[16][36];       // 2.3 KB (padded)
    __shared__ float Cs[128][33];      // 16.9 KB (padded -> conflict-free epilogue)

    const int tid = threadIdx.x;
    const int n0 = blockIdx.x * 8;

    float acc[8][4];
#pragma unroll
    for (int i = 0; i < 8; i++)
#pragma unroll
        for (int j = 0; j < 4; j++) acc[i][j] = 0.f;

    const int rg = tid >> 3;   // row group 0..15  -> rows rg*8..rg*8+7
    const int cg = tid & 7;    // col group 0..7   -> cols cg*4..cg*4+3

    if (t > 0) {
        const float* hprev = g_allh + (size_t)(t - 1) * BATCH * HID;
        const int hr = tid >> 2;            // 0..31
        const int hk = (tid & 3) * 4;       // 0/4/8/12
        const int wc = tid >> 2;            // smem gate-col 0..31  (= gate*8 + j)
        const int wk = (tid & 3) * 4;
        const int wgate = wc >> 3, wj = wc & 7;
        const float* wrow = Whh + (size_t)(wgate * HID + n0 + wj) * HID;

        for (int k0 = 0; k0 < HID; k0 += 16) {
#pragma unroll
            for (int p = 0; p < 4; p++) {
                const int r = p * 32 + hr;
                const float4 v = *reinterpret_cast<const float4*>(hprev + (size_t)r * HID + k0 + hk);
                Hs[hk + 0][r] = v.x; Hs[hk + 1][r] = v.y;
                Hs[hk + 2][r] = v.z; Hs[hk + 3][r] = v.w;
            }
            {
                const float4 w = *reinterpret_cast<const float4*>(wrow + k0 + wk);
                Ws[wk + 0][wc] = w.x; Ws[wk + 1][wc] = w.y;
                Ws[wk + 2][wc] = w.z; Ws[wk + 3][wc] = w.w;
            }
            __syncthreads();
#pragma unroll
            for (int kk = 0; kk < 16; kk++) {
                float a[8], w4[4];
                *reinterpret_cast<float4*>(&a[0]) = *reinterpret_cast<const float4*>(&Hs[kk][rg * 8]);
                *reinterpret_cast<float4*>(&a[4]) = *reinterpret_cast<const float4*>(&Hs[kk][rg * 8 + 4]);
                *reinterpret_cast<float4*>(&w4[0]) = *reinterpret_cast<const float4*>(&Ws[kk][cg * 4]);
#pragma unroll
                for (int i = 0; i < 8; i++)
#pragma unroll
                    for (int j = 0; j < 4; j++)
                        acc[i][j] = fmaf(a[i], w4[j], acc[i][j]);
            }
            __syncthreads();
        }
    }

    // Stage GEMM tile to smem so each thread owns one batch row for the cell update
#pragma unroll
    for (int i = 0; i < 8; i++)
#pragma unroll
        for (int j = 0; j < 4; j++)
            Cs[rg * 8 + i][cg * 4 + j] = acc[i][j];
    __syncthreads();

    const int b = tid;  // one thread per batch row
    const float* gpre = g_gpre + ((size_t)t * BATCH + b) * G4;
    float pre[4][8];
#pragma unroll
    for (int g = 0; g < 4; g++) {
        *reinterpret_cast<float4*>(&pre[g][0]) = *reinterpret_cast<const float4*>(gpre + g * HID + n0);
        *reinterpret_cast<float4*>(&pre[g][4]) = *reinterpret_cast<const float4*>(gpre + g * HID + n0 + 4);
    }
    float cold[8];
    if (t > 0) {
        const float* cprev = g_cbuf + (size_t)(t & 1) * BATCH * HID + (size_t)b * HID;
        *reinterpret_cast<float4*>(&cold[0]) = *reinterpret_cast<const float4*>(cprev + n0);
        *reinterpret_cast<float4*>(&cold[4]) = *reinterpret_cast<const float4*>(cprev + n0 + 4);
    } else {
#pragma unroll
        for (int j = 0; j < 8; j++) cold[j] = 0.f;
    }
    float* cnext = g_cbuf + (size_t)((t + 1) & 1) * BATCH * HID + (size_t)b * HID;
    float* hout  = g_allh + ((size_t)t * BATCH + b) * HID;

    float hn[8], cn[8];
#pragma unroll
    for (int j = 0; j < 8; j++) {
        const float gi = 1.f / (1.f + expf(-(Cs[b][0  + j] + pre[0][j])));
        const float gf = 1.f / (1.f + expf(-(Cs[b][8  + j] + pre[1][j])));
        const float gg = tanhf(Cs[b][16 + j] + pre[2][j]);
        const float go = 1.f / (1.f + expf(-(Cs[b][24 + j] + pre[3][j])));
        const float cv = gf * cold[j] + gi * gg;
        cn[j] = cv;
        hn[j] = go * tanhf(cv);
    }
    *reinterpret_cast<float4*>(cnext + n0)     = *reinterpret_cast<float4*>(&cn[0]);
    *reinterpret_cast<float4*>(cnext + n0 + 4) = *reinterpret_cast<float4*>(&cn[4]);
    *reinterpret_cast<float4*>(hout + n0)      = *reinterpret_cast<float4*>(&hn[0]);
    *reinterpret_cast<float4*>(hout + n0 + 4)  = *reinterpret_cast<float4*>(&hn[4]);
}

// ---------------------------------------------------------------------------
// Launch: gather -> input GEMM -> 24 recurrent steps -> FC GEMM (reordered out)
// ---------------------------------------------------------------------------
extern "C" void kernel_launch(void* const* d_in, const int* in_sizes, int n_in,
                              void* d_out, int out_size)
{
    const float* enc = (const float*)d_in[0];   // [128, 512]
    const int*   caps= (const int*  )d_in[1];   // [128, 24]
    const float* emb = (const float*)d_in[2];   // [12000, 512]
    const float* Wih = (const float*)d_in[3];   // [4096, 512]
    const float* Whh = (const float*)d_in[4];   // [4096, 1024]
    const float* bih = (const float*)d_in[5];   // [4096]
    const float* bhh = (const float*)d_in[6];   // [4096]
    const float* Wfc = (const float*)d_in[7];   // [12000, 1024]
    const float* bfc = (const float*)d_in[8];   // [12000]
    float* out = (float*)d_out;                 // [128, 24, 12000]

    float *xall = nullptr, *gpre = nullptr, *allh = nullptr;
    cudaGetSymbolAddress((void**)&xall, g_xall);
    cudaGetSymbolAddress((void**)&gpre, g_gpre);
    cudaGetSymbolAddress((void**)&allh, g_allh);

    // 1) gather all teacher-forced inputs
    gather_x_kernel<<<MALL, 128>>>(enc, caps, emb);

    // 2) batched input projection: G_pre = X_all @ W_ih^T + (b_ih + b_hh)
    sgemm_nt_kernel<<<dim3(G4 / 128, MALL / 128), 256>>>(
        xall, Wih, bih, bhh, gpre, MALL, G4, EMB, 0);

    // 3) sequential recurrence (only h @ W_hh^T per step)
    for (int t = 0; t < SEQT; t++)
        lstm_step_kernel<<<HID / 8, 128>>>(Whh, t);

    // 4) final FC with [b][t][v] reorder + bias
    sgemm_nt_kernel<<<dim3((VOC + 127) / 128, MALL / 128), 256>>>(
        allh, Wfc, bfc, nullptr, out, MALL, VOC, HID, 1);
}

// round 8
// speedup vs baseline: 1.5950x; 1.5950x over previous
#include <cuda_runtime.h>
#include <cuda_bf16.h>
#include <math.h>
#include <stdint.h>

constexpr int BATCH = 128, SEQT = 24, EMB = 512, HID = 1024, VOC = 12000;
constexpr int MALL = SEQT * BATCH;     // 3072, row m = t*128 + b
constexpr int G4 = 4 * HID;            // 4096
constexpr int VOCP = 12032;            // VOC padded to 128
constexpr int BK = 32;                 // K chunk
constexpr int LDT = 40;                // padded smem row stride (bf16)
constexpr int TILE_ELEMS = 128 * LDT;  // 5120 bf16 per tile
constexpr int STAGE_ELEMS = 4 * TILE_ELEMS;   // Ahi, Alo, Bhi, Blo
constexpr int STAGES = 3;
constexpr uint32_t SMEMSZ = STAGES * STAGE_ELEMS * 2;   // 122880 B

// ---------------- device scratch (allocation forbidden) ---------------------
__device__ __nv_bfloat16 g_xhi[(size_t)MALL * EMB],  g_xlo[(size_t)MALL * EMB];
__device__ __nv_bfloat16 g_wih_hi[(size_t)G4 * EMB], g_wih_lo[(size_t)G4 * EMB];
__device__ __nv_bfloat16 g_whh_hi[(size_t)G4 * HID], g_whh_lo[(size_t)G4 * HID]; // gate-interleaved
__device__ __nv_bfloat16 g_wfc_hi[(size_t)VOCP * HID], g_wfc_lo[(size_t)VOCP * HID];
__device__ __nv_bfloat16 g_hhi[(size_t)MALL * HID],  g_hlo[(size_t)MALL * HID];
__device__ float g_gpre[(size_t)MALL * G4];
__device__ float g_cbuf[2 * BATCH * HID];

// ---------------- helpers ----------------------------------------------------
__device__ __forceinline__ uint32_t smem_u32(const void* p) {
    uint32_t a;
    asm("{ .reg .u64 t; cvta.to.shared.u64 t, %1; cvt.u32.u64 %0, t; }" : "=r"(a) : "l"(p));
    return a;
}
__device__ __forceinline__ void cp16(uint32_t d, const void* s) {
    asm volatile("cp.async.cg.shared.global [%0], [%1], 16;" :: "r"(d), "l"(s));
}
__device__ __forceinline__ void cp_commit() { asm volatile("cp.async.commit_group;"); }
template <int N> __device__ __forceinline__ void cp_wait() {
    asm volatile("cp.async.wait_group %0;" :: "n"(N));
}
__device__ __forceinline__ void ldsm4(uint32_t* r, uint32_t a) {
    asm volatile("ldmatrix.sync.aligned.m8n8.x4.shared.b16 {%0,%1,%2,%3}, [%4];"
                 : "=r"(r[0]), "=r"(r[1]), "=r"(r[2]), "=r"(r[3]) : "r"(a));
}
__device__ __forceinline__ void mma16816(float* d, const uint32_t* a, const uint32_t* b) {
    asm volatile("mma.sync.aligned.m16n8k16.row.col.f32.bf16.bf16.f32 "
                 "{%0,%1,%2,%3}, {%4,%5,%6,%7}, {%8,%9}, {%0,%1,%2,%3};"
                 : "+f"(d[0]), "+f"(d[1]), "+f"(d[2]), "+f"(d[3])
                 : "r"(a[0]), "r"(a[1]), "r"(a[2]), "r"(a[3]), "r"(b[0]), "r"(b[1]));
}
__device__ __forceinline__ void split1(float x, __nv_bfloat16& hi, __nv_bfloat16& lo) {
    hi = __float2bfloat16(x);
    lo = __float2bfloat16(x - __bfloat162float(hi));
}

// ---------------- preprocessing kernels --------------------------------------
__global__ void split_plain(const float* __restrict__ s, __nv_bfloat16* __restrict__ hi,
                            __nv_bfloat16* __restrict__ lo, int n) {
    for (int i = blockIdx.x * blockDim.x + threadIdx.x; i < n; i += gridDim.x * blockDim.x)
        split1(s[i], hi[i], lo[i]);
}
// dst row d: blk=d>>7, gate=(d>>5)&3, j=d&31 ; src row = gate*HID + blk*32 + j
__global__ void split_whh(const float* __restrict__ s) {
    for (int i = blockIdx.x * blockDim.x + threadIdx.x; i < G4 * HID; i += gridDim.x * blockDim.x) {
        const int d = i >> 10, k = i & 1023;
        const int src = ((d >> 5) & 3) * HID + (d >> 7) * 32 + (d & 31);
        split1(s[(size_t)src * HID + k], g_whh_hi[i], g_whh_lo[i]);
    }
}
__global__ void split_wfc(const float* __restrict__ s) {
    for (int i = blockIdx.x * blockDim.x + threadIdx.x; i < VOCP * HID; i += gridDim.x * blockDim.x) {
        const int r = i >> 10;
        const float v = (r < VOC) ? s[i] : 0.f;
        split1(v, g_wfc_hi[i], g_wfc_lo[i]);
    }
}
__global__ void gather_split(const float* __restrict__ enc, const int* __restrict__ caps,
                             const float* __restrict__ emb) {
    const int m = blockIdx.x, t = m >> 7, b = m & 127;
    const float* src = (t == 0) ? enc + (size_t)b * EMB
                                : emb + (size_t)caps[b * SEQT + (t - 1)] * EMB;
    const float4 v = reinterpret_cast<const float4*>(src)[threadIdx.x];
    const size_t o = (size_t)m * EMB + threadIdx.x * 4;
    split1(v.x, g_xhi[o],     g_xlo[o]);
    split1(v.y, g_xhi[o + 1], g_xlo[o + 1]);
    split1(v.z, g_xhi[o + 2], g_xlo[o + 2]);
    split1(v.w, g_xhi[o + 3], g_xlo[o + 3]);
}

// ---------------- shared mainloop: acc += 3-term A[128xK] @ B[128xK]^T -------
// 256 threads, 8 warps (2M x 4N), warp tile 64x32, BK=32, 3-stage cp.async.
__device__ __forceinline__ void gemm_main(
    const __nv_bfloat16* __restrict__ Ahi, const __nv_bfloat16* __restrict__ Alo,
    const __nv_bfloat16* __restrict__ Bhi, const __nv_bfloat16* __restrict__ Blo,
    int m0, int n0, int K, uint32_t sm, float acc[4][4][4]) {
    const int tid = threadIdx.x, warp = tid >> 5, lane = tid & 31;
    const int wm = (warp & 1) * 64, wn = (warp >> 1) * 32;
    const int l8 = lane & 7, lt = lane >> 3;
    const int nk = K / BK;

    auto load_stage = [&](int stage, int k0) {
        const uint32_t sbase = sm + stage * STAGE_ELEMS * 2;
#pragma unroll
        for (int q = 0; q < 8; q++) {
            const int idx = q * 256 + tid;
            const int tile = idx >> 9, rem = idx & 511, r = rem >> 2, c = rem & 3;
            const uint32_t dst = sbase + (tile * TILE_ELEMS + r * LDT + c * 8) * 2;
            const __nv_bfloat16* src;
            if      (tile == 0) src = Ahi + (size_t)(m0 + r) * K;
            else if (tile == 1) src = Alo + (size_t)(m0 + r) * K;
            else if (tile == 2) src = Bhi + (size_t)(n0 + r) * K;
            else                src = Blo + (size_t)(n0 + r) * K;
            cp16(dst, src + k0 + c * 8);
        }
        cp_commit();
    };

    load_stage(0, 0);
    load_stage(1, BK);

    for (int kc = 0; kc < nk; kc++) {
        if (kc == nk - 1) cp_wait<0>(); else cp_wait<1>();
        __syncthreads();
        if (kc + STAGES - 1 < nk)
            load_stage((kc + STAGES - 1) % STAGES, (kc + STAGES - 1) * BK);
        const uint32_t sb = sm + (kc % STAGES) * STAGE_ELEMS * 2;
#pragma unroll
        for (int h = 0; h < 2; h++) {
            const int kk = h * 16;
            uint32_t aHi[4][4], aLo[4][4], bHi[4][2], bLo[4][2];
#pragma unroll
            for (int mi = 0; mi < 4; mi++) {
                const uint32_t ra = sb +
                    ((wm + mi * 16 + l8 + (lt & 1) * 8) * LDT + kk + (lt >> 1) * 8) * 2;
                ldsm4(aHi[mi], ra);
                ldsm4(aLo[mi], ra + TILE_ELEMS * 2);
            }
#pragma unroll
            for (int nj = 0; nj < 2; nj++) {
                const uint32_t rb = sb + 2 * TILE_ELEMS * 2 +
                    ((wn + nj * 16 + l8 + (lt >> 1) * 8) * LDT + kk + (lt & 1) * 8) * 2;
                uint32_t t4[4];
                ldsm4(t4, rb);
                bHi[nj * 2][0] = t4[0]; bHi[nj * 2][1] = t4[1];
                bHi[nj * 2 + 1][0] = t4[2]; bHi[nj * 2 + 1][1] = t4[3];
                ldsm4(t4, rb + TILE_ELEMS * 2);
                bLo[nj * 2][0] = t4[0]; bLo[nj * 2][1] = t4[1];
                bLo[nj * 2 + 1][0] = t4[2]; bLo[nj * 2 + 1][1] = t4[3];
            }
#pragma unroll
            for (int mi = 0; mi < 4; mi++)
#pragma unroll
                for (int ni = 0; ni < 4; ni++) {
                    mma16816(acc[mi][ni], aHi[mi], bHi[ni]);
                    mma16816(acc[mi][ni], aLo[mi], bHi[ni]);
                    mma16816(acc[mi][ni], aHi[mi], bLo[ni]);
                }
        }
    }
    __syncthreads();   // smem reusable by caller
}

// ---------------- generic GEMM: C = A @ B^T + bias ---------------------------
// MODE 0: row-major C[M,N], bias b1+b2.  MODE 1: m=t*128+b -> row b*24+t, bias b1, guard n<N.
template <int MODE>
__global__ __launch_bounds__(256, 1)
void mma_gemm(const __nv_bfloat16* __restrict__ Ahi, const __nv_bfloat16* __restrict__ Alo,
              const __nv_bfloat16* __restrict__ Bhi, const __nv_bfloat16* __restrict__ Blo,
              const float* __restrict__ b1, const float* __restrict__ b2,
              float* __restrict__ C, int K, int N) {
    extern __shared__ char smraw[];
    float acc[4][4][4];
#pragma unroll
    for (int a = 0; a < 4; a++)
#pragma unroll
        for (int b = 0; b < 4; b++)
#pragma unroll
            for (int c = 0; c < 4; c++) acc[a][b][c] = 0.f;

    const int m0 = blockIdx.y * 128, n0 = blockIdx.x * 128;
    gemm_main(Ahi, Alo, Bhi, Blo, m0, n0, K, smem_u32(smraw), acc);

    const int lane = threadIdx.x & 31, warp = threadIdx.x >> 5;
    const int wm = (warp & 1) * 64, wn = (warp >> 1) * 32;
    const int g = lane >> 2, tg = lane & 3;
#pragma unroll
    for (int mi = 0; mi < 4; mi++)
#pragma unroll
        for (int half = 0; half < 2; half++) {
            const int m = m0 + wm + mi * 16 + g + half * 8;
            const size_t rowBase = (MODE == 0)
                ? (size_t)m * N
                : ((size_t)(m & 127) * SEQT + (size_t)(m >> 7)) * N;
#pragma unroll
            for (int ni = 0; ni < 4; ni++) {
                const int n = n0 + wn + ni * 8 + tg * 2;
                if (MODE == 1 && n >= N) continue;
                const float2 bb = *reinterpret_cast<const float2*>(b1 + n);
                float2 v;
                v.x = acc[mi][ni][half * 2 + 0] + bb.x;
                v.y = acc[mi][ni][half * 2 + 1] + bb.y;
                if (MODE == 0) {
                    const float2 b2v = *reinterpret_cast<const float2*>(b2 + n);
                    v.x += b2v.x; v.y += b2v.y;
                }
                *reinterpret_cast<float2*>(C + rowBase + n) = v;
            }
        }
}

// ---------------- recurrent step: MMA + fused LSTM cell ----------------------
// CTA blk covers hidden [blk*32, blk*32+32); gate-interleaved W_hh rows mean
// D col = gate*32 + j. Stage acc -> smem, then 2 threads per batch row update.
__global__ __launch_bounds__(256, 1)
void lstm_mma_step(int t) {
    extern __shared__ char smraw[];
    const int tid = threadIdx.x, blk = blockIdx.x;
    float* Cs = reinterpret_cast<float*>(smraw);   // [128][132]

    if (t > 0) {
        float acc[4][4][4];
#pragma unroll
        for (int a = 0; a < 4; a++)
#pragma unroll
            for (int b = 0; b < 4; b++)
#pragma unroll
                for (int c = 0; c < 4; c++) acc[a][b][c] = 0.f;
        gemm_main(g_hhi + (size_t)(t - 1) * BATCH * HID,
                  g_hlo + (size_t)(t - 1) * BATCH * HID,
                  g_whh_hi, g_whh_lo, 0, blk * 128, HID, smem_u32(smraw), acc);
        const int lane = tid & 31, warp = tid >> 5;
        const int wm = (warp & 1) * 64, wn = (warp >> 1) * 32;
        const int g = lane >> 2, tg = lane & 3;
#pragma unroll
        for (int mi = 0; mi < 4; mi++)
#pragma unroll
            for (int half = 0; half < 2; half++) {
                const int r = wm + mi * 16 + g + half * 8;
#pragma unroll
                for (int ni = 0; ni < 4; ni++) {
                    const int cidx = wn + ni * 8 + tg * 2;
                    float2 v;
                    v.x = acc[mi][ni][half * 2 + 0];
                    v.y = acc[mi][ni][half * 2 + 1];
                    *reinterpret_cast<float2*>(&Cs[r * 132 + cidx]) = v;
                }
            }
        __syncthreads();
    }

    // cell update: thread pair per batch row; jh = 16-col half
    const int b = tid >> 1, jh = (tid & 1) * 16;
    const float* gp   = g_gpre + ((size_t)t * BATCH + b) * G4 + blk * 32;
    const float* cold = g_cbuf + (size_t)(t & 1) * BATCH * HID + (size_t)b * HID + blk * 32;
    float*       cnew = g_cbuf + (size_t)((t + 1) & 1) * BATCH * HID + (size_t)b * HID + blk * 32;
    __nv_bfloat16* hh = g_hhi + ((size_t)t * BATCH + b) * HID + blk * 32;
    __nv_bfloat16* hl = g_hlo + ((size_t)t * BATCH + b) * HID + blk * 32;

#pragma unroll
    for (int j = 0; j < 16; j++) {
        const int jj = jh + j;
        float ai = 0.f, af = 0.f, ag = 0.f, ao = 0.f;
        if (t > 0) {
            ai = Cs[b * 132 + 0  + jj];
            af = Cs[b * 132 + 32 + jj];
            ag = Cs[b * 132 + 64 + jj];
            ao = Cs[b * 132 + 96 + jj];
        }
        const float gi = 1.f / (1.f + expf(-(ai + gp[0 * HID + jj])));
        const float gf = 1.f / (1.f + expf(-(af + gp[1 * HID + jj])));
        const float gg = tanhf(ag + gp[2 * HID + jj]);
        const float go = 1.f / (1.f + expf(-(ao + gp[3 * HID + jj])));
        const float cv = gf * ((t > 0) ? cold[jj] : 0.f) + gi * gg;
        const float hv = go * tanhf(cv);
        cnew[jj] = cv;
        split1(hv, hh[jj], hl[jj]);
    }
}

// ---------------- launch ------------------------------------------------------
extern "C" void kernel_launch(void* const* d_in, const int* in_sizes, int n_in,
                              void* d_out, int out_size) {
    const float* enc  = (const float*)d_in[0];
    const int*   caps = (const int*  )d_in[1];
    const float* emb  = (const float*)d_in[2];
    const float* Wih  = (const float*)d_in[3];
    const float* Whh  = (const float*)d_in[4];
    const float* bih  = (const float*)d_in[5];
    const float* bhh  = (const float*)d_in[6];
    const float* Wfc  = (const float*)d_in[7];
    const float* bfc  = (const float*)d_in[8];
    float* out = (float*)d_out;

    cudaFuncSetAttribute(mma_gemm<0>, cudaFuncAttributeMaxDynamicSharedMemorySize, SMEMSZ);
    cudaFuncSetAttribute(mma_gemm<1>, cudaFuncAttributeMaxDynamicSharedMemorySize, SMEMSZ);
    cudaFuncSetAttribute(lstm_mma_step, cudaFuncAttributeMaxDynamicSharedMemorySize, SMEMSZ);

    void* p;
#define SYM(v, s) cudaGetSymbolAddress(&p, s); __nv_bfloat16* v = (__nv_bfloat16*)p;
    SYM(xhi, g_xhi)       SYM(xlo, g_xlo)
    SYM(wih_hi, g_wih_hi) SYM(wih_lo, g_wih_lo)
    SYM(wfc_hi, g_wfc_hi) SYM(wfc_lo, g_wfc_lo)
    SYM(hhi, g_hhi)       SYM(hlo, g_hlo)
#undef SYM
    cudaGetSymbolAddress(&p, g_gpre);
    float* gpre = (float*)p;

    gather_split<<<MALL, 128>>>(enc, caps, emb);
    split_plain<<<296, 256>>>(Wih, wih_hi, wih_lo, G4 * EMB);
    split_whh<<<296, 256>>>(Whh);
    split_wfc<<<296, 256>>>(Wfc);

    // input projection: G_pre = X @ W_ih^T + b_ih + b_hh   [3072, 4096]
    mma_gemm<0><<<dim3(G4 / 128, MALL / 128), 256, SMEMSZ>>>(
        xhi, xlo, wih_hi, wih_lo, bih, bhh, gpre, EMB, G4);

    for (int t = 0; t < SEQT; t++)
        lstm_mma_step<<<HID / 32, 256, SMEMSZ>>>(t);

    // FC: logits[b,t,:] = h @ W_fc^T + b_fc   (N padded to 12032, guarded)
    mma_gemm<1><<<dim3(VOCP / 128, MALL / 128), 256, SMEMSZ>>>(
        hhi, hlo, wfc_hi, wfc_lo, bfc, nullptr, out, HID, VOC);
}

// round 9
// speedup vs baseline: 2.6798x; 1.6801x over previous
#include <cuda_runtime.h>
#include <cuda_bf16.h>
#include <math.h>
#include <stdint.h>

constexpr int BATCH = 128, SEQT = 24, EMB = 512, HID = 1024, VOC = 12000;
constexpr int MALL = SEQT * BATCH;     // 3072, row m = t*128 + b
constexpr int G4 = 4 * HID;            // 4096
constexpr int VOCP = 12032;            // VOC padded to 128
constexpr int BK = 32;                 // K chunk
constexpr int LDT = 40;                // padded smem row stride (bf16)
constexpr int STAGES = 3;
constexpr int TA = 128 * LDT;          // A tile elems (rows always 128)
// big GEMM (NT=128): stage = 2*TA + 2*(128*LDT)
constexpr uint32_t SMEMSZ   = STAGES * (2 * TA + 2 * 128 * LDT) * 2;  // 122880 B
// lstm GEMM (NT=32):  stage = 2*TA + 2*(32*LDT)
constexpr uint32_t SMEMSZ_L = STAGES * (2 * TA + 2 * 32 * LDT) * 2;   // 76800 B

// ---------------- device scratch (allocation forbidden) ---------------------
__device__ __nv_bfloat16 g_xhi[(size_t)MALL * EMB],  g_xlo[(size_t)MALL * EMB];
__device__ __nv_bfloat16 g_wih_hi[(size_t)G4 * EMB], g_wih_lo[(size_t)G4 * EMB];
__device__ __nv_bfloat16 g_whh_hi[(size_t)G4 * HID], g_whh_lo[(size_t)G4 * HID]; // interleaved, see split_whh4
__device__ __nv_bfloat16 g_wfc_hi[(size_t)VOCP * HID], g_wfc_lo[(size_t)VOCP * HID];
__device__ __nv_bfloat16 g_hhi[(size_t)MALL * HID],  g_hlo[(size_t)MALL * HID];
__device__ float g_gpre[(size_t)MALL * G4];
__device__ float g_cbuf[2 * BATCH * HID];

// ---------------- helpers ----------------------------------------------------
__device__ __forceinline__ uint32_t smem_u32(const void* p) {
    uint32_t a;
    asm("{ .reg .u64 t; cvta.to.shared.u64 t, %1; cvt.u32.u64 %0, t; }" : "=r"(a) : "l"(p));
    return a;
}
__device__ __forceinline__ void cp16(uint32_t d, const void* s) {
    asm volatile("cp.async.cg.shared.global [%0], [%1], 16;" :: "r"(d), "l"(s));
}
__device__ __forceinline__ void cp_commit() { asm volatile("cp.async.commit_group;"); }
template <int N> __device__ __forceinline__ void cp_wait() {
    asm volatile("cp.async.wait_group %0;" :: "n"(N));
}
__device__ __forceinline__ void ldsm4(uint32_t* r, uint32_t a) {
    asm volatile("ldmatrix.sync.aligned.m8n8.x4.shared.b16 {%0,%1,%2,%3}, [%4];"
                 : "=r"(r[0]), "=r"(r[1]), "=r"(r[2]), "=r"(r[3]) : "r"(a));
}
__device__ __forceinline__ void mma16816(float* d, const uint32_t* a, const uint32_t* b) {
    asm volatile("mma.sync.aligned.m16n8k16.row.col.f32.bf16.bf16.f32 "
                 "{%0,%1,%2,%3}, {%4,%5,%6,%7}, {%8,%9}, {%0,%1,%2,%3};"
                 : "+f"(d[0]), "+f"(d[1]), "+f"(d[2]), "+f"(d[3])
                 : "r"(a[0]), "r"(a[1]), "r"(a[2]), "r"(a[3]), "r"(b[0]), "r"(b[1]));
}
__device__ __forceinline__ void split1(float x, __nv_bfloat16& hi, __nv_bfloat16& lo) {
    hi = __float2bfloat16(x);
    lo = __float2bfloat16(x - __bfloat162float(hi));
}
__device__ __forceinline__ uint32_t pack2(__nv_bfloat16 a, __nv_bfloat16 b) {
    __nv_bfloat162 p = __halves2bfloat162(a, b);
    return *reinterpret_cast<uint32_t*>(&p);
}
__device__ __forceinline__ void split4(float4 v, uint2& hi, uint2& lo) {
    __nv_bfloat16 h0, l0, h1, l1, h2, l2, h3, l3;
    split1(v.x, h0, l0); split1(v.y, h1, l1);
    split1(v.z, h2, l2); split1(v.w, h3, l3);
    hi = make_uint2(pack2(h0, h1), pack2(h2, h3));
    lo = make_uint2(pack2(l0, l1), pack2(l2, l3));
}

// ---------------- preprocessing (vectorized) ----------------------------------
__global__ void split_plain4(const float* __restrict__ s, __nv_bfloat16* __restrict__ hi,
                             __nv_bfloat16* __restrict__ lo, int n4) {
    for (int i = blockIdx.x * blockDim.x + threadIdx.x; i < n4; i += gridDim.x * blockDim.x) {
        uint2 uh, ul;
        split4(reinterpret_cast<const float4*>(s)[i], uh, ul);
        reinterpret_cast<uint2*>(hi)[i] = uh;
        reinterpret_cast<uint2*>(lo)[i] = ul;
    }
}
// W_hh interleave for 128-CTA recurrence: dst row d -> blk=d>>5, gate=(d>>3)&3,
// j=d&7 ; src row = gate*HID + blk*8 + j
__global__ void split_whh4(const float* __restrict__ s) {
    constexpr int N4 = G4 * HID / 4;
    for (int i = blockIdx.x * blockDim.x + threadIdx.x; i < N4; i += gridDim.x * blockDim.x) {
        const int d = i >> 8, k4 = i & 255;
        const int src = ((d >> 3) & 3) * HID + (d >> 5) * 8 + (d & 7);
        uint2 uh, ul;
        split4(*reinterpret_cast<const float4*>(s + (size_t)src * HID + k4 * 4), uh, ul);
        reinterpret_cast<uint2*>(g_whh_hi)[i] = uh;
        reinterpret_cast<uint2*>(g_whh_lo)[i] = ul;
    }
}
__global__ void split_wfc4(const float* __restrict__ s) {
    constexpr int N4 = VOCP * HID / 4;
    for (int i = blockIdx.x * blockDim.x + threadIdx.x; i < N4; i += gridDim.x * blockDim.x) {
        const int r = i >> 8;
        float4 v = (r < VOC) ? reinterpret_cast<const float4*>(s)[i]
                             : make_float4(0.f, 0.f, 0.f, 0.f);
        uint2 uh, ul;
        split4(v, uh, ul);
        reinterpret_cast<uint2*>(g_wfc_hi)[i] = uh;
        reinterpret_cast<uint2*>(g_wfc_lo)[i] = ul;
    }
}
__global__ void gather_split(const float* __restrict__ enc, const int* __restrict__ caps,
                             const float* __restrict__ emb) {
    const int m = blockIdx.x, t = m >> 7, b = m & 127;
    const float* src = (t == 0) ? enc + (size_t)b * EMB
                                : emb + (size_t)caps[b * SEQT + (t - 1)] * EMB;
    const float4 v = reinterpret_cast<const float4*>(src)[threadIdx.x];
    const int i = m * (EMB / 4) + threadIdx.x;
    uint2 uh, ul;
    split4(v, uh, ul);
    reinterpret_cast<uint2*>(g_xhi)[i] = uh;
    reinterpret_cast<uint2*>(g_xlo)[i] = ul;
}

// ---------------- templated mainloop: acc += 3-term A[128xK] @ B[NTxK]^T -----
// 256 threads, 8 warps. NT=128: warps 2Mx4N (wt 64x32, MI=NI=4).
//                       NT=32 : warps 4Mx2N (wt 32x16, MI=NI=2).
template <int NT, int MI, int NI>
__device__ __forceinline__ void gemm_main(
    const __nv_bfloat16* __restrict__ Ahi, const __nv_bfloat16* __restrict__ Alo,
    const __nv_bfloat16* __restrict__ Bhi, const __nv_bfloat16* __restrict__ Blo,
    int m0, int n0, int K, uint32_t sm, float (&acc)[MI][NI][4]) {
    constexpr int TB = NT * LDT;
    constexpr int STAGE = 2 * TA + 2 * TB;
    constexpr int TOT = (128 * 2 + NT * 2) * 4;     // cp16 per stage

    const int tid = threadIdx.x, warp = tid >> 5, lane = tid & 31;
    const int wm = (NT == 128) ? (warp & 1) * 64 : (warp & 3) * 32;
    const int wn = (NT == 128) ? (warp >> 1) * 32 : (warp >> 2) * 16;
    const int l8 = lane & 7, lt = lane >> 3;
    const int nk = K / BK;

    auto load_stage = [&](int stage, int k0) {
        const uint32_t sbase = sm + stage * STAGE * 2;
#pragma unroll
        for (int idx = tid; idx < TOT; idx += 256) {
            uint32_t dst;
            const __nv_bfloat16* src;
            if (idx < 512) {
                const int r = idx >> 2, c = idx & 3;
                dst = sbase + (r * LDT + c * 8) * 2;
                src = Ahi + (size_t)(m0 + r) * K + k0 + c * 8;
            } else if (idx < 1024) {
                const int j = idx - 512, r = j >> 2, c = j & 3;
                dst = sbase + (TA + r * LDT + c * 8) * 2;
                src = Alo + (size_t)(m0 + r) * K + k0 + c * 8;
            } else if (idx < 1024 + NT * 4) {
                const int j = idx - 1024, r = j >> 2, c = j & 3;
                dst = sbase + (2 * TA + r * LDT + c * 8) * 2;
                src = Bhi + (size_t)(n0 + r) * K + k0 + c * 8;
            } else {
                const int j = idx - 1024 - NT * 4, r = j >> 2, c = j & 3;
                dst = sbase + (2 * TA + TB + r * LDT + c * 8) * 2;
                src = Blo + (size_t)(n0 + r) * K + k0 + c * 8;
            }
            cp16(dst, src);
        }
        cp_commit();
    };

    load_stage(0, 0);
    load_stage(1, BK);

    for (int kc = 0; kc < nk; kc++) {
        if (kc == nk - 1) cp_wait<0>(); else cp_wait<1>();
        __syncthreads();
        if (kc + STAGES - 1 < nk)
            load_stage((kc + STAGES - 1) % STAGES, (kc + STAGES - 1) * BK);
        const uint32_t sb = sm + (kc % STAGES) * STAGE * 2;
#pragma unroll
        for (int h = 0; h < 2; h++) {
            const int kk = h * 16;
            uint32_t aHi[MI][4], aLo[MI][4], bHi[NI][2], bLo[NI][2];
#pragma unroll
            for (int mi = 0; mi < MI; mi++) {
                const uint32_t ra = sb +
                    ((wm + mi * 16 + l8 + (lt & 1) * 8) * LDT + kk + (lt >> 1) * 8) * 2;
                ldsm4(aHi[mi], ra);
                ldsm4(aLo[mi], ra + TA * 2);
            }
#pragma unroll
            for (int nj = 0; nj < NI / 2; nj++) {
                const uint32_t rb = sb + 2 * TA * 2 +
                    ((wn + nj * 16 + l8 + (lt >> 1) * 8) * LDT + kk + (lt & 1) * 8) * 2;
                uint32_t t4[4];
                ldsm4(t4, rb);
                bHi[nj * 2][0] = t4[0]; bHi[nj * 2][1] = t4[1];
                bHi[nj * 2 + 1][0] = t4[2]; bHi[nj * 2 + 1][1] = t4[3];
                ldsm4(t4, rb + TB * 2);
                bLo[nj * 2][0] = t4[0]; bLo[nj * 2][1] = t4[1];
                bLo[nj * 2 + 1][0] = t4[2]; bLo[nj * 2 + 1][1] = t4[3];
            }
#pragma unroll
            for (int mi = 0; mi < MI; mi++)
#pragma unroll
                for (int ni = 0; ni < NI; ni++) {
                    mma16816(acc[mi][ni], aHi[mi], bHi[ni]);
                    mma16816(acc[mi][ni], aLo[mi], bHi[ni]);
                    mma16816(acc[mi][ni], aHi[mi], bLo[ni]);
                }
        }
    }
    __syncthreads();   // smem reusable by caller
}

// ---------------- generic GEMM: C = A @ B^T + bias ---------------------------
// MODE 0: row-major C[M,N], bias b1+b2.  MODE 1: m=t*128+b -> row b*24+t, bias b1, guard n<N.
template <int MODE>
__global__ __launch_bounds__(256, 1)
void mma_gemm(const __nv_bfloat16* __restrict__ Ahi, const __nv_bfloat16* __restrict__ Alo,
              const __nv_bfloat16* __restrict__ Bhi, const __nv_bfloat16* __restrict__ Blo,
              const float* __restrict__ b1, const float* __restrict__ b2,
              float* __restrict__ C, int K, int N) {
    extern __shared__ char smraw[];
    float acc[4][4][4];
#pragma unroll
    for (int a = 0; a < 4; a++)
#pragma unroll
        for (int b = 0; b < 4; b++)
#pragma unroll
            for (int c = 0; c < 4; c++) acc[a][b][c] = 0.f;

    const int m0 = blockIdx.y * 128, n0 = blockIdx.x * 128;
    gemm_main<128, 4, 4>(Ahi, Alo, Bhi, Blo, m0, n0, K, smem_u32(smraw), acc);

    const int lane = threadIdx.x & 31, warp = threadIdx.x >> 5;
    const int wm = (warp & 1) * 64, wn = (warp >> 1) * 32;
    const int g = lane >> 2, tg = lane & 3;
#pragma unroll
    for (int mi = 0; mi < 4; mi++)
#pragma unroll
        for (int half = 0; half < 2; half++) {
            const int m = m0 + wm + mi * 16 + g + half * 8;
            const size_t rowBase = (MODE == 0)
                ? (size_t)m * N
                : ((size_t)(m & 127) * SEQT + (size_t)(m >> 7)) * N;
#pragma unroll
            for (int ni = 0; ni < 4; ni++) {
                const int n = n0 + wn + ni * 8 + tg * 2;
                if (MODE == 1 && n >= N) continue;
                const float2 bb = *reinterpret_cast<const float2*>(b1 + n);
                float2 v;
                v.x = acc[mi][ni][half * 2 + 0] + bb.x;
                v.y = acc[mi][ni][half * 2 + 1] + bb.y;
                if (MODE == 0) {
                    const float2 b2v = *reinterpret_cast<const float2*>(b2 + n);
                    v.x += b2v.x; v.y += b2v.y;
                }
                *reinterpret_cast<float2*>(C + rowBase + n) = v;
            }
        }
}

// ---------------- recurrent step: 128 CTAs, tile [128 x 32], fused cell ------
// CTA blk covers hidden [blk*8, blk*8+8) x 4 gates; interleaved W_hh rows mean
// D col c = gate*8 + j (gate=c>>3, j=c&7). Two threads per batch row update.
__global__ __launch_bounds__(256, 1)
void lstm_mma_step(int t) {
    extern __shared__ char smraw[];
    const int tid = threadIdx.x, blk = blockIdx.x;
    float* Cs = reinterpret_cast<float*>(smraw);   // [128][36]

    if (t > 0) {
        float acc[2][2][4];
#pragma unroll
        for (int a = 0; a < 2; a++)
#pragma unroll
            for (int b = 0; b < 2; b++)
#pragma unroll
                for (int c = 0; c < 4; c++) acc[a][b][c] = 0.f;
        gemm_main<32, 2, 2>(g_hhi + (size_t)(t - 1) * BATCH * HID,
                            g_hlo + (size_t)(t - 1) * BATCH * HID,
                            g_whh_hi, g_whh_lo, 0, blk * 32, HID,
                            smem_u32(smraw), acc);
        const int lane = tid & 31, warp = tid >> 5;
        const int wm = (warp & 3) * 32, wn = (warp >> 2) * 16;
        const int g = lane >> 2, tg = lane & 3;
#pragma unroll
        for (int mi = 0; mi < 2; mi++)
#pragma unroll
            for (int half = 0; half < 2; half++) {
                const int r = wm + mi * 16 + g + half * 8;
#pragma unroll
                for (int ni = 0; ni < 2; ni++) {
                    const int c = wn + ni * 8 + tg * 2;
                    float2 v;
                    v.x = acc[mi][ni][half * 2 + 0];
                    v.y = acc[mi][ni][half * 2 + 1];
                    *reinterpret_cast<float2*>(&Cs[r * 36 + c]) = v;
                }
            }
        __syncthreads();
    }

    // cell update: 2 threads per batch row, 4 hidden units each
    const int b = tid >> 1, hs = (tid & 1) * 4;    // hidden sub-offset 0 or 4
    const int j0 = blk * 8;
    const float* gp   = g_gpre + ((size_t)t * BATCH + b) * G4;
    const float* cold = g_cbuf + (size_t)(t & 1) * BATCH * HID + (size_t)b * HID;
    float*       cnew = g_cbuf + (size_t)((t + 1) & 1) * BATCH * HID + (size_t)b * HID;
    __nv_bfloat16* hh = g_hhi + ((size_t)t * BATCH + b) * HID;
    __nv_bfloat16* hl = g_hlo + ((size_t)t * BATCH + b) * HID;

    const float4 pi = *reinterpret_cast<const float4*>(gp + 0 * HID + j0 + hs);
    const float4 pf = *reinterpret_cast<const float4*>(gp + 1 * HID + j0 + hs);
    const float4 pg = *reinterpret_cast<const float4*>(gp + 2 * HID + j0 + hs);
    const float4 po = *reinterpret_cast<const float4*>(gp + 3 * HID + j0 + hs);
    float4 co = make_float4(0.f, 0.f, 0.f, 0.f);
    if (t > 0) co = *reinterpret_cast<const float4*>(cold + j0 + hs);

    float cn[4], hn[4];
#pragma unroll
    for (int q = 0; q < 4; q++) {
        float ai = 0.f, af = 0.f, ag = 0.f, ao = 0.f;
        if (t > 0) {
            ai = Cs[b * 36 + 0  + hs + q];
            af = Cs[b * 36 + 8  + hs + q];
            ag = Cs[b * 36 + 16 + hs + q];
            ao = Cs[b * 36 + 24 + hs + q];
        }
        const float* pip = &pi.x;
        const float* pfp = &pf.x;
        const float* pgp = &pg.x;
        const float* pop = &po.x;
        const float* cop = &co.x;
        const float gi = 1.f / (1.f + expf(-(ai + pip[q])));
        const float gf = 1.f / (1.f + expf(-(af + pfp[q])));
        const float gg = tanhf(ag + pgp[q]);
        const float go = 1.f / (1.f + expf(-(ao + pop[q])));
        const float cv = gf * cop[q] + gi * gg;
        cn[q] = cv;
        hn[q] = go * tanhf(cv);
    }
    *reinterpret_cast<float4*>(cnew + j0 + hs) = make_float4(cn[0], cn[1], cn[2], cn[3]);
    __nv_bfloat16 h0, l0, h1, l1, h2, l2, h3, l3;
    split1(hn[0], h0, l0); split1(hn[1], h1, l1);
    split1(hn[2], h2, l2); split1(hn[3], h3, l3);
    *reinterpret_cast<uint2*>(hh + j0 + hs) = make_uint2(pack2(h0, h1), pack2(h2, h3));
    *reinterpret_cast<uint2*>(hl + j0 + hs) = make_uint2(pack2(l0, l1), pack2(l2, l3));
}

// ---------------- launch ------------------------------------------------------
extern "C" void kernel_launch(void* const* d_in, const int* in_sizes, int n_in,
                              void* d_out, int out_size) {
    const float* enc  = (const float*)d_in[0];
    const int*   caps = (const int*  )d_in[1];
    const float* emb  = (const float*)d_in[2];
    const float* Wih  = (const float*)d_in[3];
    const float* Whh  = (const float*)d_in[4];
    const float* bih  = (const float*)d_in[5];
    const float* bhh  = (const float*)d_in[6];
    const float* Wfc  = (const float*)d_in[7];
    const float* bfc  = (const float*)d_in[8];
    float* out = (float*)d_out;

    cudaFuncSetAttribute(mma_gemm<0>, cudaFuncAttributeMaxDynamicSharedMemorySize, SMEMSZ);
    cudaFuncSetAttribute(mma_gemm<1>, cudaFuncAttributeMaxDynamicSharedMemorySize, SMEMSZ);
    cudaFuncSetAttribute(lstm_mma_step, cudaFuncAttributeMaxDynamicSharedMemorySize, SMEMSZ_L);

    void* p;
#define SYM(v, s) cudaGetSymbolAddress(&p, s); __nv_bfloat16* v = (__nv_bfloat16*)p;
    SYM(xhi, g_xhi)       SYM(xlo, g_xlo)
    SYM(wih_hi, g_wih_hi) SYM(wih_lo, g_wih_lo)
    SYM(wfc_hi, g_wfc_hi) SYM(wfc_lo, g_wfc_lo)
    SYM(hhi, g_hhi)       SYM(hlo, g_hlo)
#undef SYM
    cudaGetSymbolAddress(&p, g_gpre);
    float* gpre = (float*)p;

    gather_split<<<MALL, 128>>>(enc, caps, emb);
    split_plain4<<<1024, 256>>>(Wih, wih_hi, wih_lo, G4 * EMB / 4);
    split_whh4<<<2048, 256>>>(Whh);
    split_wfc4<<<2048, 256>>>(Wfc);

    // input projection: G_pre = X @ W_ih^T + b_ih + b_hh   [3072, 4096]
    mma_gemm<0><<<dim3(G4 / 128, MALL / 128), 256, SMEMSZ>>>(
        xhi, xlo, wih_hi, wih_lo, bih, bhh, gpre, EMB, G4);

    for (int t = 0; t < SEQT; t++)
        lstm_mma_step<<<128, 256, SMEMSZ_L>>>(t);

    // FC: logits[b,t,:] = h @ W_fc^T + b_fc   (N padded to 12032, guarded)
    mma_gemm<1><<<dim3(VOCP / 128, MALL / 128), 256, SMEMSZ>>>(
        hhi, hlo, wfc_hi, wfc_lo, bfc, nullptr, out, HID, VOC);
}